// round 4
// baseline (speedup 1.0000x reference)
#include <cuda_runtime.h>
#include <cuda_bf16.h>

static constexpr int N = 256;
static constexpr int B = 512;
static constexpr int M = N * (N - 1) / 2;  // 32640

__device__ __forceinline__ float sqrt_approx(float x) {
    float r;
    asm("sqrt.approx.f32 %0, %1;" : "=f"(r) : "f"(x));
    return r;
}

// One column step of the reference recurrence, reproducing its rounding:
//   t = 1 - rowsum ; x2 = (z*z) * t ; rowsum = rowsum + x2 ; out = sqrt(x2)*sign(z)
// __fadd_rn/__fmul_rn prevent FMA contraction so the fp32 op sequence matches
// the reference's unfused mul/add (critical for the deep-column plateau of
// 1-rowsum, which the reference relies on).
__device__ __forceinline__ float chol_step(float z, float& rowsum) {
    float t  = __fadd_rn(1.0f, -rowsum);
    float z2 = __fmul_rn(z, z);
    float x2 = __fmul_rn(z2, t);
    rowsum   = __fadd_rn(rowsum, x2);
    return copysignf(sqrt_approx(x2), z);
}

// OFS = (row base offset) & 3. Input is read via 16B-aligned float4 loads with
// a rolling funnel window; output via float4 stores (row base is 1KB aligned).
template <int OFS>
__device__ __forceinline__ void do_row(const float* __restrict__ zrow,
                                       float* __restrict__ orow, int i) {
    float rowsum = 0.0f;
    float4* __restrict__ o4 = reinterpret_cast<float4*>(orow);
    int j = 0;

    if (i >= 4) {
        const float4* __restrict__ a4 =
            reinterpret_cast<const float4*>(zrow - OFS);
        float4 cur = a4[0];
        int q = 1;
        for (; j + 4 <= i; j += 4) {
            float e0, e1, e2, e3;
            if (OFS == 0) {
                e0 = cur.x; e1 = cur.y; e2 = cur.z; e3 = cur.w;
                if (j + 8 <= i) cur = a4[q++];  // never read past the last needed quad
            } else {
                float4 nxt = a4[q++];
                if (OFS == 1)      { e0 = cur.y; e1 = cur.z; e2 = cur.w; e3 = nxt.x; }
                else if (OFS == 2) { e0 = cur.z; e1 = cur.w; e2 = nxt.x; e3 = nxt.y; }
                else               { e0 = cur.w; e1 = nxt.x; e2 = nxt.y; e3 = nxt.z; }
                cur = nxt;
            }
            float4 o;
            o.x = chol_step(e0, rowsum);
            o.y = chol_step(e1, rowsum);
            o.z = chol_step(e2, rowsum);
            o.w = chol_step(e3, rowsum);
            o4[j >> 2] = o;
        }
    }

    // Boundary quad: remaining scan elements (j..i-1), diagonal 1 at i, zeros after.
    // Loads are predicated so we never read beyond the row/buffer end.
    {
        float4 o;
        o.x = (j + 0 < i) ? chol_step(zrow[j + 0], rowsum)
                          : ((j + 0 == i) ? 1.0f : 0.0f);
        o.y = (j + 1 < i) ? chol_step(zrow[j + 1], rowsum)
                          : ((j + 1 == i) ? 1.0f : 0.0f);
        o.z = (j + 2 < i) ? chol_step(zrow[j + 2], rowsum)
                          : ((j + 2 == i) ? 1.0f : 0.0f);
        o.w = (j + 3 < i) ? chol_step(zrow[j + 3], rowsum)
                          : ((j + 3 == i) ? 1.0f : 0.0f);
        o4[j >> 2] = o;
    }

    // Zero fill the rest of the row (strict upper triangle).
    for (int qq = (j >> 2) + 1; qq < N / 4; ++qq)
        o4[qq] = make_float4(0.0f, 0.0f, 0.0f, 0.0f);
}

__global__ void __launch_bounds__(128)
chol_from_z_kernel(const float* __restrict__ vec, float* __restrict__ out) {
    // Longest rows first (blockIdx.x = 0 -> row 255) so the triangular load
    // balances across waves via work-stealing.
    int i = (N - 1) - (int)blockIdx.x;
    int b = (int)blockIdx.y * (int)blockDim.x + (int)threadIdx.x;

    int tri = (i * (i - 1)) >> 1;  // start of row i in the packed vec
    const float* zrow = vec + (size_t)b * M + tri;
    float* orow = out + ((size_t)b * N + i) * (size_t)N;

    switch (tri & 3) {  // uniform across the block (same i)
        case 0:  do_row<0>(zrow, orow, i); break;
        case 1:  do_row<1>(zrow, orow, i); break;
        case 2:  do_row<2>(zrow, orow, i); break;
        default: do_row<3>(zrow, orow, i); break;
    }
}

extern "C" void kernel_launch(void* const* d_in, const int* in_sizes, int n_in,
                              void* d_out, int out_size) {
    const float* vec = (const float*)d_in[0];
    float* out = (float*)d_out;
    dim3 grid(N, B / 128);
    chol_from_z_kernel<<<grid, 128>>>(vec, out);
}